// round 1
// baseline (speedup 1.0000x reference)
#include <cuda_runtime.h>

// RoPE over x:(B=4, H=32, S=8192, D=64) fp32, token_position = arange(S).
// Strategy:
//   Kernel 1: build cos/sin table (S x D/2) once per launch into a __device__
//             global (2 MB). Double-precision sincos of the fp32-rounded angle
//             to match the fp32 JAX reference closely. ~262K threads, cheap.
//   Kernel 2: streaming elementwise rotate, one float4 (= 2 pairs) per thread.
//             Table fetch is L2-resident (128x reuse per entry).

#define S_LEN   8192
#define HALF_D  32          // D/2
#define LOG2_THETA 13.287712379549449  // log2(10000)

__device__ float2 g_rope_tbl[S_LEN * HALF_D];   // (cos, sin) per (s, j)

__global__ void rope_build_table(const int* __restrict__ token_position, int total) {
    int t = blockIdx.x * blockDim.x + threadIdx.x;
    if (t >= total) return;
    int s = t >> 5;           // position-list index
    int j = t & 31;           // frequency index
    float pos = (float)token_position[s];
    // inv_freq = theta^(-2j/64), computed in double then rounded to fp32
    double invd = exp2(-(double)(2 * j) / 64.0 * LOG2_THETA);
    float inv = (float)invd;
    // angle rounded to fp32 (reference computes ang in fp32), then accurate sincos
    float ang = pos * inv;
    double sd, cd;
    sincos((double)ang, &sd, &cd);
    g_rope_tbl[t] = make_float2((float)cd, (float)sd);
}

__global__ void rope_rotate(const float4* __restrict__ x,
                            float4* __restrict__ out, int n4) {
    int i = blockIdx.x * blockDim.x + threadIdx.x;
    if (i >= n4) return;
    int within = i & 15;              // which float4 within the 64-elem row
    int row    = i >> 4;              // (b*H + h)*S + s
    int s      = row & (S_LEN - 1);   // S is power of two

    float4 v = x[i];
    // table packed as float2 pairs; two consecutive j -> one aligned float4
    const float4* tbl4 = reinterpret_cast<const float4*>(g_rope_tbl);
    float4 cs = tbl4[s * (HALF_D / 2) + within];  // (c0, s0, c1, s1)

    float4 r;
    r.x = v.x * cs.x - v.y * cs.y;
    r.y = v.x * cs.y + v.y * cs.x;
    r.z = v.z * cs.z - v.w * cs.w;
    r.w = v.z * cs.w + v.w * cs.z;
    out[i] = r;
}

extern "C" void kernel_launch(void* const* d_in, const int* in_sizes, int n_in,
                              void* d_out, int out_size) {
    const float* x   = (const float*)d_in[0];
    const int*   tok = (const int*)d_in[1];
    int n  = in_sizes[0];       // total elements (67,108,864)
    int P  = in_sizes[1];       // number of positions (8192)
    int n4 = n / 4;

    int tbl_total = P * HALF_D;
    rope_build_table<<<(tbl_total + 255) / 256, 256>>>(tok, tbl_total);

    rope_rotate<<<(n4 + 255) / 256, 256>>>((const float4*)x, (float4*)d_out, n4);
}

// round 2
// speedup vs baseline: 1.1697x; 1.1697x over previous
#include <cuda_runtime.h>

// RoPE over x:(B=4, H=32, S=8192, D=64) fp32, token_position = arange(S).
//   Kernel 1: build (cos,sin) table (S x 32) -> 2 MB __device__ global.
//             fp32 sincosf of the fp32-rounded angle (matches fp32 reference
//             to ~2 ulp); inv_freq in double so the angle rounding matches.
//   Kernel 2: streaming rotate, 2x float4 per thread, .cs hints on the
//             bulk stream so the table stays L2-resident.

#define S_LEN   8192
#define HALF_D  32
#define LOG2_THETA 13.287712379549449  // log2(10000)

__device__ float2 g_rope_tbl[S_LEN * HALF_D];

__global__ void rope_build_table(const int* __restrict__ token_position, int total) {
    int t = blockIdx.x * blockDim.x + threadIdx.x;
    if (t >= total) return;
    int s = t >> 5;           // position index
    int j = t & 31;           // frequency index
    float pos = (float)token_position[s];
    // inv_freq in double, rounded to fp32 (matches fp32 theta**(-2j/d) to 1 ulp)
    float inv = (float)exp2(-(double)(2 * j) / 64.0 * LOG2_THETA);
    float ang = pos * inv;    // fp32 angle, same rounding as reference
    float sn, cn;
    sincosf(ang, &sn, &cn);   // accurate fp32 path (Payne-Hanek for large args)
    g_rope_tbl[t] = make_float2(cn, sn);
}

__global__ void __launch_bounds__(256)
rope_rotate(const float4* __restrict__ x, float4* __restrict__ out, int n4) {
    int i0 = (blockIdx.x * blockDim.x + threadIdx.x) * 2;
    const float4* tbl4 = reinterpret_cast<const float4*>(g_rope_tbl);

    float4 v[2], cs[2];
    #pragma unroll
    for (int k = 0; k < 2; k++) {
        int i = i0 + k;
        if (i < n4) {
            int within = i & 15;            // float4 index within 64-elem row
            int s = (i >> 4) & (S_LEN - 1); // sequence position
            v[k]  = __ldcs(&x[i]);          // evict-first: pure stream
            cs[k] = __ldg(&tbl4[s * (HALF_D / 2) + within]); // keep cached
        }
    }
    #pragma unroll
    for (int k = 0; k < 2; k++) {
        int i = i0 + k;
        if (i < n4) {
            float4 r;
            r.x = v[k].x * cs[k].x - v[k].y * cs[k].y;
            r.y = v[k].x * cs[k].y + v[k].y * cs[k].x;
            r.z = v[k].z * cs[k].z - v[k].w * cs[k].w;
            r.w = v[k].z * cs[k].w + v[k].w * cs[k].z;
            __stcs(&out[i], r);
        }
    }
}

extern "C" void kernel_launch(void* const* d_in, const int* in_sizes, int n_in,
                              void* d_out, int out_size) {
    const float* x   = (const float*)d_in[0];
    const int*   tok = (const int*)d_in[1];
    int n  = in_sizes[0];      // 67,108,864 elements
    int P  = in_sizes[1];      // 8192 positions
    int n4 = n / 4;

    int tbl_total = P * HALF_D;
    rope_build_table<<<(tbl_total + 255) / 256, 256>>>(tok, tbl_total);

    int threads = 256;
    int work_per_block = threads * 2;
    int blocks = (n4 + work_per_block - 1) / work_per_block;
    rope_rotate<<<blocks, threads>>>((const float4*)x, (float4*)d_out, n4);
}